// round 1
// baseline (speedup 1.0000x reference)
#include <cuda_runtime.h>
#include <math.h>

#define NNODES 50000
#define NEDGES 800000
#define ETOT   (NEDGES + NNODES)
#define DIN    256
#define HID    128

// ---------------- scratch (static device globals; no allocation) -------------
__device__ float g_XLR[NNODES * 256];   // fused [xl | xr] per node (51.2 MB)
__device__ float g_H[NNODES * HID];     // layer output (25.6 MB)
__device__ int   g_deg[NNODES];
__device__ int   g_off[NNODES + 1];
__device__ int   g_cur[NNODES];
__device__ int   g_csr[ETOT];

// ---------------- CSR build --------------------------------------------------
__global__ void k_deg_init() {
    int i = blockIdx.x * blockDim.x + threadIdx.x;
    if (i < NNODES) g_deg[i] = 1;   // self loop
}

__global__ void k_deg_count(const int* __restrict__ ei) {
    int e = blockIdx.x * blockDim.x + threadIdx.x;
    if (e < NEDGES) atomicAdd(&g_deg[ei[NEDGES + e]], 1);
}

// single-block exclusive scan of g_deg -> g_off, copy to g_cur
__global__ void k_scan() {
    __shared__ int sh[1024];
    const int n = NNODES;
    int tid = threadIdx.x;
    const int chunk = (n + 1023) / 1024;    // 49
    int start = tid * chunk;
    int s = 0;
    for (int i = 0; i < chunk; i++) {
        int idx = start + i;
        if (idx < n) s += g_deg[idx];
    }
    sh[tid] = s;
    __syncthreads();
    for (int o = 1; o < 1024; o <<= 1) {
        int v = (tid >= o) ? sh[tid - o] : 0;
        __syncthreads();
        sh[tid] += v;
        __syncthreads();
    }
    int run = tid ? sh[tid - 1] : 0;
    for (int i = 0; i < chunk; i++) {
        int idx = start + i;
        if (idx < n) {
            g_off[idx] = run;
            g_cur[idx] = run;
            run += g_deg[idx];
        }
    }
    if (tid == 1023) g_off[n] = sh[1023];
}

__global__ void k_fill(const int* __restrict__ ei) {
    int e = blockIdx.x * blockDim.x + threadIdx.x;
    if (e >= ETOT) return;
    int src, dst;
    if (e < NEDGES) { src = ei[e]; dst = ei[NEDGES + e]; }
    else            { src = dst = e - NEDGES; }
    int pos = atomicAdd(&g_cur[dst], 1);
    g_csr[pos] = src;
}

// ---------------- fused xl|xr GEMM: Out[M,256] = X[M,K] @ [Wl;Wr]^T ----------
// 64x64 block tile, 256 threads, 4x4 micro-tile, K-tile 16
__global__ void k_gemm_xlr(const float* __restrict__ X,
                           const float* __restrict__ Wl,
                           const float* __restrict__ Wr,
                           float* __restrict__ Out, int K) {
    __shared__ float As[16][68];
    __shared__ float Bs[16][68];
    int tid = threadIdx.x;
    int m0 = blockIdx.x * 64, n0 = blockIdx.y * 64;
    int ty = tid >> 4, tx = tid & 15;
    int lrow = tid >> 2;            // 0..63
    int kq = (tid & 3) << 2;        // 0,4,8,12
    float acc[4][4] = {};

    int j = n0 + lrow;
    const float* wbase = (j < 128) ? (Wl + (long)j * K) : (Wr + (long)(j - 128) * K);
    int gm = m0 + lrow;
    bool mval = (gm < NNODES);
    const float* xbase = X + (long)(mval ? gm : 0) * K;

    for (int k0 = 0; k0 < K; k0 += 16) {
        float4 av = mval ? *(const float4*)(xbase + k0 + kq) : make_float4(0.f, 0.f, 0.f, 0.f);
        float4 bv = *(const float4*)(wbase + k0 + kq);
        As[kq + 0][lrow] = av.x; As[kq + 1][lrow] = av.y;
        As[kq + 2][lrow] = av.z; As[kq + 3][lrow] = av.w;
        Bs[kq + 0][lrow] = bv.x; Bs[kq + 1][lrow] = bv.y;
        Bs[kq + 2][lrow] = bv.z; Bs[kq + 3][lrow] = bv.w;
        __syncthreads();
#pragma unroll
        for (int k = 0; k < 16; k++) {
            float4 a = *(const float4*)&As[k][ty << 2];
            float4 b = *(const float4*)&Bs[k][tx << 2];
            acc[0][0] += a.x * b.x; acc[0][1] += a.x * b.y; acc[0][2] += a.x * b.z; acc[0][3] += a.x * b.w;
            acc[1][0] += a.y * b.x; acc[1][1] += a.y * b.y; acc[1][2] += a.y * b.z; acc[1][3] += a.y * b.w;
            acc[2][0] += a.z * b.x; acc[2][1] += a.z * b.y; acc[2][2] += a.z * b.z; acc[2][3] += a.z * b.w;
            acc[3][0] += a.w * b.x; acc[3][1] += a.w * b.y; acc[3][2] += a.w * b.z; acc[3][3] += a.w * b.w;
        }
        __syncthreads();
    }
#pragma unroll
    for (int i = 0; i < 4; i++) {
        int gr = m0 + (ty << 2) + i;
        if (gr < NNODES) {
            float4 v = make_float4(acc[i][0], acc[i][1], acc[i][2], acc[i][3]);
            *(float4*)(Out + (long)gr * 256 + n0 + (tx << 2)) = v;
        }
    }
}

// ---------------- GATv2 attention, warp-per-dst, online softmax --------------
// XLR layout: [n][0..127]=xl, [n][128..255]=xr. Lane l handles element h*32+l.
__global__ void k_attn(const float* __restrict__ XLR,
                       const float* __restrict__ att,
                       const float* __restrict__ bias,
                       float* __restrict__ H) {
    int warp = (blockIdx.x * blockDim.x + threadIdx.x) >> 5;
    int lane = threadIdx.x & 31;
    if (warp >= NNODES) return;
    int dst = warp;

    const float* xr = XLR + (long)dst * 256 + 128;
    float xr0 = xr[lane], xr1 = xr[32 + lane], xr2 = xr[64 + lane], xr3 = xr[96 + lane];
    float a0 = att[lane], a1 = att[32 + lane], a2 = att[64 + lane], a3 = att[96 + lane];

    int beg = g_off[dst], end = g_off[dst + 1];

    float m0 = -1e30f, m1 = -1e30f, m2 = -1e30f, m3 = -1e30f;
    float s0 = 0.f, s1 = 0.f, s2 = 0.f, s3 = 0.f;

    for (int jj = beg; jj < end; jj++) {
        int src = g_csr[jj];
        const float* xl = XLR + (long)src * 256;
        float t0 = xl[lane] + xr0, t1 = xl[32 + lane] + xr1;
        float t2 = xl[64 + lane] + xr2, t3 = xl[96 + lane] + xr3;
        t0 = (t0 > 0.f) ? t0 : 0.2f * t0;
        t1 = (t1 > 0.f) ? t1 : 0.2f * t1;
        t2 = (t2 > 0.f) ? t2 : 0.2f * t2;
        t3 = (t3 > 0.f) ? t3 : 0.2f * t3;
        float p0 = a0 * t0, p1 = a1 * t1, p2 = a2 * t2, p3 = a3 * t3;
#pragma unroll
        for (int o = 16; o; o >>= 1) {
            p0 += __shfl_xor_sync(0xffffffffu, p0, o);
            p1 += __shfl_xor_sync(0xffffffffu, p1, o);
            p2 += __shfl_xor_sync(0xffffffffu, p2, o);
            p3 += __shfl_xor_sync(0xffffffffu, p3, o);
        }
        float nm;
        nm = fmaxf(m0, p0); s0 = s0 * __expf(m0 - nm) + __expf(p0 - nm); m0 = nm;
        nm = fmaxf(m1, p1); s1 = s1 * __expf(m1 - nm) + __expf(p1 - nm); m1 = nm;
        nm = fmaxf(m2, p2); s2 = s2 * __expf(m2 - nm) + __expf(p2 - nm); m2 = nm;
        nm = fmaxf(m3, p3); s3 = s3 * __expf(m3 - nm) + __expf(p3 - nm); m3 = nm;
    }
    float i0 = 1.f / s0, i1 = 1.f / s1, i2 = 1.f / s2, i3 = 1.f / s3;

    float c0 = 0.f, c1 = 0.f, c2 = 0.f, c3 = 0.f;
    for (int jj = beg; jj < end; jj++) {
        int src = g_csr[jj];
        const float* xl = XLR + (long)src * 256;
        float l0 = xl[lane], l1 = xl[32 + lane], l2 = xl[64 + lane], l3 = xl[96 + lane];
        float t0 = l0 + xr0, t1 = l1 + xr1, t2 = l2 + xr2, t3 = l3 + xr3;
        t0 = (t0 > 0.f) ? t0 : 0.2f * t0;
        t1 = (t1 > 0.f) ? t1 : 0.2f * t1;
        t2 = (t2 > 0.f) ? t2 : 0.2f * t2;
        t3 = (t3 > 0.f) ? t3 : 0.2f * t3;
        float p0 = a0 * t0, p1 = a1 * t1, p2 = a2 * t2, p3 = a3 * t3;
#pragma unroll
        for (int o = 16; o; o >>= 1) {
            p0 += __shfl_xor_sync(0xffffffffu, p0, o);
            p1 += __shfl_xor_sync(0xffffffffu, p1, o);
            p2 += __shfl_xor_sync(0xffffffffu, p2, o);
            p3 += __shfl_xor_sync(0xffffffffu, p3, o);
        }
        float al0 = __expf(p0 - m0) * i0;
        float al1 = __expf(p1 - m1) * i1;
        float al2 = __expf(p2 - m2) * i2;
        float al3 = __expf(p3 - m3) * i3;
        c0 += al0 * l0; c1 += al1 * l1; c2 += al2 * l2; c3 += al3 * l3;
    }
    float* hp = H + (long)dst * 128;
    hp[lane]      = c0 + bias[lane];
    hp[32 + lane] = c1 + bias[32 + lane];
    hp[64 + lane] = c2 + bias[64 + lane];
    hp[96 + lane] = c3 + bias[96 + lane];
}

// ---------------- down projection: Out[N,32] = H[N,128] @ W[32,128]^T + b ----
__global__ void k_down(const float* __restrict__ Hin,
                       const float* __restrict__ W,
                       const float* __restrict__ b,
                       float* __restrict__ Out) {
    __shared__ float Ws[128 * 33];   // Ws[k*33 + c], conflict-free
    __shared__ float Hs[8 * 128];
    int tid = threadIdx.x;
    for (int l = tid; l < 32 * 128; l += 256) {
        int c = l / 128, k = l % 128;
        Ws[k * 33 + c] = W[l];
    }
    int n0 = blockIdx.x * 8;
    for (int l = tid; l < 8 * 128; l += 256)
        Hs[l] = Hin[(long)n0 * 128 + l];
    __syncthreads();
    int nd = tid >> 5, c = tid & 31;
    float acc = 0.f;
#pragma unroll 16
    for (int k = 0; k < 128; k++)
        acc += Hs[nd * 128 + k] * Ws[k * 33 + c];
    Out[(long)(n0 + nd) * 32 + c] = acc + b[c];
}

// ---------------- launch -----------------------------------------------------
extern "C" void kernel_launch(void* const* d_in, const int* in_sizes, int n_in,
                              void* d_out, int out_size) {
    const float* x    = (const float*)d_in[0];
    const int*   ei   = (const int*)d_in[1];
    const float* Wl0  = (const float*)d_in[2];
    const float* Wr0  = (const float*)d_in[3];
    const float* att0 = (const float*)d_in[4];
    const float* b0   = (const float*)d_in[5];
    const float* Wl1  = (const float*)d_in[6];
    const float* Wr1  = (const float*)d_in[7];
    const float* att1 = (const float*)d_in[8];
    const float* b1   = (const float*)d_in[9];
    const float* dW   = (const float*)d_in[10];
    const float* db   = (const float*)d_in[11];
    float* out = (float*)d_out;

    float *xlr_p = nullptr, *h_p = nullptr;
    cudaGetSymbolAddress((void**)&xlr_p, g_XLR);
    cudaGetSymbolAddress((void**)&h_p, g_H);

    // CSR build (identical for both layers)
    k_deg_init<<<(NNODES + 255) / 256, 256>>>();
    k_deg_count<<<(NEDGES + 255) / 256, 256>>>(ei);
    k_scan<<<1, 1024>>>();
    k_fill<<<(ETOT + 255) / 256, 256>>>(ei);

    dim3 gg((NNODES + 63) / 64, 4);

    // layer 0
    k_gemm_xlr<<<gg, 256>>>(x, Wl0, Wr0, xlr_p, DIN);
    k_attn<<<(NNODES * 32 + 255) / 256, 256>>>(xlr_p, att0, b0, h_p);

    // layer 1
    k_gemm_xlr<<<gg, 256>>>(h_p, Wl1, Wr1, xlr_p, HID);
    k_attn<<<(NNODES * 32 + 255) / 256, 256>>>(xlr_p, att1, b1, h_p);

    // down proj
    k_down<<<NNODES / 8, 256>>>(h_p, dW, db, out);
}

// round 2
// speedup vs baseline: 1.5449x; 1.5449x over previous
#include <cuda_runtime.h>
#include <math.h>

#define NNODES 50000
#define NEDGES 800000
#define ETOT   (NEDGES + NNODES)
#define DIN    256
#define HID    128

// ---------------- scratch (static device globals; no allocation) -------------
__device__ float g_XLR[NNODES * 256];   // fused [xl | xr] per node (51.2 MB)
__device__ float g_H[NNODES * HID];     // layer output (25.6 MB)
__device__ int   g_deg[NNODES];
__device__ int   g_off[NNODES + 1];
__device__ int   g_cur[NNODES];
__device__ int   g_csr[ETOT];

// ---------------- CSR build --------------------------------------------------
__global__ void k_deg_init() {
    int i = blockIdx.x * blockDim.x + threadIdx.x;
    if (i < NNODES) g_deg[i] = 1;   // self loop
}

__global__ void k_deg_count(const int* __restrict__ ei) {
    int e = blockIdx.x * blockDim.x + threadIdx.x;
    if (e < NEDGES) atomicAdd(&g_deg[ei[NEDGES + e]], 1);
}

// single-block exclusive scan of g_deg -> g_off, copy to g_cur
__global__ void k_scan() {
    __shared__ int sh[1024];
    const int n = NNODES;
    int tid = threadIdx.x;
    const int chunk = (n + 1023) / 1024;    // 49
    int start = tid * chunk;
    int s = 0;
    for (int i = 0; i < chunk; i++) {
        int idx = start + i;
        if (idx < n) s += g_deg[idx];
    }
    sh[tid] = s;
    __syncthreads();
    for (int o = 1; o < 1024; o <<= 1) {
        int v = (tid >= o) ? sh[tid - o] : 0;
        __syncthreads();
        sh[tid] += v;
        __syncthreads();
    }
    int run = tid ? sh[tid - 1] : 0;
    for (int i = 0; i < chunk; i++) {
        int idx = start + i;
        if (idx < n) {
            g_off[idx] = run;
            g_cur[idx] = run;
            run += g_deg[idx];
        }
    }
    if (tid == 1023) g_off[n] = sh[1023];
}

__global__ void k_fill(const int* __restrict__ ei) {
    int e = blockIdx.x * blockDim.x + threadIdx.x;
    if (e >= ETOT) return;
    int src, dst;
    if (e < NEDGES) { src = ei[e]; dst = ei[NEDGES + e]; }
    else            { src = dst = e - NEDGES; }
    int pos = atomicAdd(&g_cur[dst], 1);
    g_csr[pos] = src;
}

// ---------------- fused xl|xr GEMM: Out[M,256] = X[M,K] @ [Wl;Wr]^T ----------
// 128x128 block tile, 256 threads, 8x8 micro-tile, BK=8, double-buffered smem.
#define SM_LD 132
__global__ void __launch_bounds__(256)
k_gemm_xlr(const float* __restrict__ X,
           const float* __restrict__ Wl,
           const float* __restrict__ Wr,
           float* __restrict__ Out, int K) {
    __shared__ float As[2][8][SM_LD];
    __shared__ float Bs[2][8][SM_LD];
    int t = threadIdx.x;
    int m0 = blockIdx.x * 128, n0 = blockIdx.y * 128;
    int lr = t >> 1;             // 0..127
    int lc = (t & 1) << 2;       // 0 or 4
    int ty = t >> 4, tx = t & 15;

    int grow = m0 + lr;
    bool aval = (grow < NNODES);
    const float* ap = X + (size_t)(aval ? grow : 0) * K + lc;
    int ncol = n0 + lr;          // 0..255
    const float* wp = ((ncol < 128) ? (Wl + (size_t)ncol * K)
                                    : (Wr + (size_t)(ncol - 128) * K)) + lc;

    const float4 zero4 = make_float4(0.f, 0.f, 0.f, 0.f);
    float4 a = aval ? *(const float4*)ap : zero4;
    float4 b = *(const float4*)wp;
    As[0][lc + 0][lr] = a.x; As[0][lc + 1][lr] = a.y;
    As[0][lc + 2][lr] = a.z; As[0][lc + 3][lr] = a.w;
    Bs[0][lc + 0][lr] = b.x; Bs[0][lc + 1][lr] = b.y;
    Bs[0][lc + 2][lr] = b.z; Bs[0][lc + 3][lr] = b.w;
    __syncthreads();

    float acc[8][8];
#pragma unroll
    for (int i = 0; i < 8; i++)
#pragma unroll
        for (int j = 0; j < 8; j++) acc[i][j] = 0.f;

    int nk = K >> 3;
    for (int kt = 0; kt < nk; kt++) {
        int buf = kt & 1;
        float4 an = zero4, bn = zero4;
        if (kt + 1 < nk) {
            if (aval) an = *(const float4*)(ap + (size_t)(kt + 1) * 8);
            bn = *(const float4*)(wp + (size_t)(kt + 1) * 8);
        }
#pragma unroll
        for (int k = 0; k < 8; k++) {
            float4 a0 = *(const float4*)&As[buf][k][ty * 8];
            float4 a1 = *(const float4*)&As[buf][k][ty * 8 + 4];
            float4 b0 = *(const float4*)&Bs[buf][k][tx * 8];
            float4 b1 = *(const float4*)&Bs[buf][k][tx * 8 + 4];
            float ar[8] = {a0.x, a0.y, a0.z, a0.w, a1.x, a1.y, a1.z, a1.w};
            float br[8] = {b0.x, b0.y, b0.z, b0.w, b1.x, b1.y, b1.z, b1.w};
#pragma unroll
            for (int i = 0; i < 8; i++)
#pragma unroll
                for (int j = 0; j < 8; j++)
                    acc[i][j] += ar[i] * br[j];
        }
        if (kt + 1 < nk) {
            int nb = (kt + 1) & 1;
            As[nb][lc + 0][lr] = an.x; As[nb][lc + 1][lr] = an.y;
            As[nb][lc + 2][lr] = an.z; As[nb][lc + 3][lr] = an.w;
            Bs[nb][lc + 0][lr] = bn.x; Bs[nb][lc + 1][lr] = bn.y;
            Bs[nb][lc + 2][lr] = bn.z; Bs[nb][lc + 3][lr] = bn.w;
        }
        __syncthreads();
    }

#pragma unroll
    for (int i = 0; i < 8; i++) {
        int gr = m0 + ty * 8 + i;
        if (gr < NNODES) {
            float4 v0 = make_float4(acc[i][0], acc[i][1], acc[i][2], acc[i][3]);
            float4 v1 = make_float4(acc[i][4], acc[i][5], acc[i][6], acc[i][7]);
            float* op = Out + (size_t)gr * 256 + n0 + tx * 8;
            *(float4*)op = v0;
            *(float4*)(op + 4) = v1;
        }
    }
}

// ---------------- GATv2 attention: warp-per-dst, single-pass flash softmax ---
// XLR layout: [n][0..127]=xl, [n][128..255]=xr.
// Lane l handles contiguous channels 4l..4l+3 (all within head l>>3).
// Per-head logit reduce = 3 shfl.xor within the 8-lane group.
__global__ void k_attn(const float* __restrict__ XLR,
                       const float* __restrict__ att,
                       const float* __restrict__ bias,
                       float* __restrict__ H) {
    int warp = (blockIdx.x * blockDim.x + threadIdx.x) >> 5;
    int lane = threadIdx.x & 31;
    if (warp >= NNODES) return;
    int dst = warp;
    int c4 = lane << 2;

    float4 xr = *(const float4*)(XLR + (size_t)dst * 256 + 128 + c4);
    float4 av = *(const float4*)(att + c4);

    int beg = g_off[dst], end = g_off[dst + 1];

    float m = -1e30f, s = 0.f;
    float cx = 0.f, cy = 0.f, cz = 0.f, cw = 0.f;

    int src0 = g_csr[beg];
    float4 v = *(const float4*)(XLR + (size_t)src0 * 256 + c4);

    for (int jj = beg; jj < end; jj++) {
        float4 vn = v;
        if (jj + 1 < end) {
            int sn = g_csr[jj + 1];
            vn = *(const float4*)(XLR + (size_t)sn * 256 + c4);
        }
        float t0 = v.x + xr.x, t1 = v.y + xr.y, t2 = v.z + xr.z, t3 = v.w + xr.w;
        t0 = (t0 > 0.f) ? t0 : 0.2f * t0;
        t1 = (t1 > 0.f) ? t1 : 0.2f * t1;
        t2 = (t2 > 0.f) ? t2 : 0.2f * t2;
        t3 = (t3 > 0.f) ? t3 : 0.2f * t3;
        float p = av.x * t0 + av.y * t1 + av.z * t2 + av.w * t3;
        p += __shfl_xor_sync(0xffffffffu, p, 1);
        p += __shfl_xor_sync(0xffffffffu, p, 2);
        p += __shfl_xor_sync(0xffffffffu, p, 4);

        float nm = fmaxf(m, p);
        float sc = __expf(m - nm);
        float w  = __expf(p - nm);
        s  = s * sc + w;
        cx = cx * sc + w * v.x;
        cy = cy * sc + w * v.y;
        cz = cz * sc + w * v.z;
        cw = cw * sc + w * v.w;
        m = nm;
        v = vn;
    }
    float inv = 1.f / s;
    float4 bv = *(const float4*)(bias + c4);
    float4 o = make_float4(cx * inv + bv.x, cy * inv + bv.y,
                           cz * inv + bv.z, cw * inv + bv.w);
    *(float4*)(H + (size_t)dst * 128 + c4) = o;
}

// ---------------- down projection: Out[N,32] = H[N,128] @ W[32,128]^T + b ----
__global__ void k_down(const float* __restrict__ Hin,
                       const float* __restrict__ W,
                       const float* __restrict__ b,
                       float* __restrict__ Out) {
    __shared__ float Ws[128 * 33];   // Ws[k*33 + c], conflict-free
    __shared__ float Hs[8 * 128];
    int tid = threadIdx.x;
    for (int l = tid; l < 32 * 128; l += 256) {
        int c = l / 128, k = l % 128;
        Ws[k * 33 + c] = W[l];
    }
    int n0 = blockIdx.x * 8;
    for (int l = tid; l < 8 * 128; l += 256)
        Hs[l] = Hin[(size_t)n0 * 128 + l];
    __syncthreads();
    int nd = tid >> 5, c = tid & 31;
    float acc = 0.f;
#pragma unroll 16
    for (int k = 0; k < 128; k++)
        acc += Hs[nd * 128 + k] * Ws[k * 33 + c];
    Out[(size_t)(n0 + nd) * 32 + c] = acc + b[c];
}

// ---------------- launch -----------------------------------------------------
extern "C" void kernel_launch(void* const* d_in, const int* in_sizes, int n_in,
                              void* d_out, int out_size) {
    const float* x    = (const float*)d_in[0];
    const int*   ei   = (const int*)d_in[1];
    const float* Wl0  = (const float*)d_in[2];
    const float* Wr0  = (const float*)d_in[3];
    const float* att0 = (const float*)d_in[4];
    const float* b0   = (const float*)d_in[5];
    const float* Wl1  = (const float*)d_in[6];
    const float* Wr1  = (const float*)d_in[7];
    const float* att1 = (const float*)d_in[8];
    const float* b1   = (const float*)d_in[9];
    const float* dW   = (const float*)d_in[10];
    const float* db   = (const float*)d_in[11];
    float* out = (float*)d_out;

    float *xlr_p = nullptr, *h_p = nullptr;
    cudaGetSymbolAddress((void**)&xlr_p, g_XLR);
    cudaGetSymbolAddress((void**)&h_p, g_H);

    // CSR build (identical for both layers)
    k_deg_init<<<(NNODES + 255) / 256, 256>>>();
    k_deg_count<<<(NEDGES + 255) / 256, 256>>>(ei);
    k_scan<<<1, 1024>>>();
    k_fill<<<(ETOT + 255) / 256, 256>>>(ei);

    dim3 gg((NNODES + 127) / 128, 2);

    // layer 0
    k_gemm_xlr<<<gg, 256>>>(x, Wl0, Wr0, xlr_p, DIN);
    k_attn<<<(NNODES * 32 + 255) / 256, 256>>>(xlr_p, att0, b0, h_p);

    // layer 1
    k_gemm_xlr<<<gg, 256>>>(h_p, Wl1, Wr1, xlr_p, HID);
    k_attn<<<(NNODES * 32 + 255) / 256, 256>>>(xlr_p, att1, b1, h_p);

    // down proj
    k_down<<<NNODES / 8, 256>>>(h_p, dW, db, out);
}

// round 3
// speedup vs baseline: 1.9449x; 1.2589x over previous
#include <cuda_runtime.h>
#include <math.h>

#define NNODES 50000
#define NEDGES 800000
#define ETOT   (NEDGES + NNODES)
#define DIN    256
#define HID    128

// ---------------- scratch (static device globals; no allocation) -------------
__device__ float g_XLR[NNODES * 256];   // fused [xl | xr] per node (51.2 MB)
__device__ float g_H[NNODES * HID];     // layer output (25.6 MB)
__device__ int   g_deg[NNODES];
__device__ int   g_off[NNODES + 1];
__device__ int   g_cur[NNODES];
__device__ int   g_csr[ETOT];

// ---------------- CSR build --------------------------------------------------
__global__ void k_deg_init() {
    int i = blockIdx.x * blockDim.x + threadIdx.x;
    if (i < NNODES) g_deg[i] = 1;   // self loop
}

__global__ void k_deg_count(const int* __restrict__ ei) {
    int e = blockIdx.x * blockDim.x + threadIdx.x;
    if (e < NEDGES) atomicAdd(&g_deg[ei[NEDGES + e]], 1);
}

// single-block exclusive scan of g_deg -> g_off, copy to g_cur
__global__ void k_scan() {
    __shared__ int sh[1024];
    const int n = NNODES;
    int tid = threadIdx.x;
    const int chunk = (n + 1023) / 1024;    // 49
    int start = tid * chunk;
    int s = 0;
    for (int i = 0; i < chunk; i++) {
        int idx = start + i;
        if (idx < n) s += g_deg[idx];
    }
    sh[tid] = s;
    __syncthreads();
    for (int o = 1; o < 1024; o <<= 1) {
        int v = (tid >= o) ? sh[tid - o] : 0;
        __syncthreads();
        sh[tid] += v;
        __syncthreads();
    }
    int run = tid ? sh[tid - 1] : 0;
    for (int i = 0; i < chunk; i++) {
        int idx = start + i;
        if (idx < n) {
            g_off[idx] = run;
            g_cur[idx] = run;
            run += g_deg[idx];
        }
    }
    if (tid == 1023) g_off[n] = sh[1023];
}

__global__ void k_fill(const int* __restrict__ ei) {
    int e = blockIdx.x * blockDim.x + threadIdx.x;
    if (e >= ETOT) return;
    int src, dst;
    if (e < NEDGES) { src = ei[e]; dst = ei[NEDGES + e]; }
    else            { src = dst = e - NEDGES; }
    int pos = atomicAdd(&g_cur[dst], 1);
    g_csr[pos] = src;
}

// ---------------- TF32 tensor-core GEMM: Out[M,256] = X[M,K] @ [Wl;Wr]^T -----
// 128x128 block tile, 256 threads (8 warps, 2x4), 64x32 warp tile,
// K-chunk 16, double-buffered k-major smem (ld=136 words, conflict-free).
#define GLD 136

__device__ __forceinline__ unsigned f2tf32(float f) {
    unsigned u;
    asm("cvt.rna.tf32.f32 %0, %1;" : "=r"(u) : "f"(f));
    return u;
}

__global__ void __launch_bounds__(256)
k_gemm_tf32(const float* __restrict__ X,
            const float* __restrict__ Wl,
            const float* __restrict__ Wr,
            float* __restrict__ Out, int K) {
    __shared__ unsigned As[2][16][GLD];
    __shared__ unsigned Bs[2][16][GLD];
    int t = threadIdx.x;
    int m0 = blockIdx.x * 128, n0 = blockIdx.y * 128;
    int mi = t & 127;
    int half = t >> 7;          // 0 or 1
    int lane = t & 31;
    int wid = t >> 5;
    int wm = (wid >> 2) * 64;   // 0 or 64
    int wn = (wid & 3) * 32;    // 0,32,64,96
    int g = lane >> 2, c = lane & 3;

    bool aval = (m0 + mi) < NNODES;
    const float* ap = X + (size_t)(aval ? (m0 + mi) : 0) * K;
    const float* wp = ((n0 == 0) ? Wl : Wr) + (size_t)mi * K;

    float acc[4][4][4];
#pragma unroll
    for (int i = 0; i < 4; i++)
#pragma unroll
        for (int j = 0; j < 4; j++)
#pragma unroll
            for (int q = 0; q < 4; q++) acc[i][j][q] = 0.f;

    const float4 z4 = make_float4(0.f, 0.f, 0.f, 0.f);
    int nk = K >> 4;   // K/16 tiles

    // prologue: tile 0
    float4 pa[2], pb[2];
#pragma unroll
    for (int i = 0; i < 2; i++) {
        int k4 = half * 8 + i * 4;
        pa[i] = aval ? *(const float4*)(ap + k4) : z4;
        pb[i] = *(const float4*)(wp + k4);
    }
#pragma unroll
    for (int i = 0; i < 2; i++) {
        int k4 = half * 8 + i * 4;
        As[0][k4 + 0][mi] = f2tf32(pa[i].x); As[0][k4 + 1][mi] = f2tf32(pa[i].y);
        As[0][k4 + 2][mi] = f2tf32(pa[i].z); As[0][k4 + 3][mi] = f2tf32(pa[i].w);
        Bs[0][k4 + 0][mi] = f2tf32(pb[i].x); Bs[0][k4 + 1][mi] = f2tf32(pb[i].y);
        Bs[0][k4 + 2][mi] = f2tf32(pb[i].z); Bs[0][k4 + 3][mi] = f2tf32(pb[i].w);
    }
    __syncthreads();

    for (int kt = 0; kt < nk; kt++) {
        int buf = kt & 1;
        if (kt + 1 < nk) {
            int kb = (kt + 1) * 16;
#pragma unroll
            for (int i = 0; i < 2; i++) {
                int k4 = kb + half * 8 + i * 4;
                pa[i] = aval ? *(const float4*)(ap + k4) : z4;
                pb[i] = *(const float4*)(wp + k4);
            }
        }
#pragma unroll
        for (int s = 0; s < 2; s++) {
            int ks = s * 8;
            unsigned bf[4][2];
#pragma unroll
            for (int j = 0; j < 4; j++) {
                bf[j][0] = Bs[buf][ks + c][wn + j * 8 + g];
                bf[j][1] = Bs[buf][ks + c + 4][wn + j * 8 + g];
            }
#pragma unroll
            for (int i = 0; i < 4; i++) {
                unsigned a0 = As[buf][ks + c][wm + i * 16 + g];
                unsigned a1 = As[buf][ks + c][wm + i * 16 + g + 8];
                unsigned a2 = As[buf][ks + c + 4][wm + i * 16 + g];
                unsigned a3 = As[buf][ks + c + 4][wm + i * 16 + g + 8];
#pragma unroll
                for (int j = 0; j < 4; j++) {
                    asm volatile(
                        "mma.sync.aligned.m16n8k8.row.col.f32.tf32.tf32.f32 "
                        "{%0,%1,%2,%3}, {%4,%5,%6,%7}, {%8,%9}, {%0,%1,%2,%3};"
                        : "+f"(acc[i][j][0]), "+f"(acc[i][j][1]),
                          "+f"(acc[i][j][2]), "+f"(acc[i][j][3])
                        : "r"(a0), "r"(a1), "r"(a2), "r"(a3),
                          "r"(bf[j][0]), "r"(bf[j][1]));
                }
            }
        }
        if (kt + 1 < nk) {
            int nb = (kt + 1) & 1;
#pragma unroll
            for (int i = 0; i < 2; i++) {
                int k4 = half * 8 + i * 4;
                As[nb][k4 + 0][mi] = f2tf32(pa[i].x); As[nb][k4 + 1][mi] = f2tf32(pa[i].y);
                As[nb][k4 + 2][mi] = f2tf32(pa[i].z); As[nb][k4 + 3][mi] = f2tf32(pa[i].w);
                Bs[nb][k4 + 0][mi] = f2tf32(pb[i].x); Bs[nb][k4 + 1][mi] = f2tf32(pb[i].y);
                Bs[nb][k4 + 2][mi] = f2tf32(pb[i].z); Bs[nb][k4 + 3][mi] = f2tf32(pb[i].w);
            }
        }
        __syncthreads();
    }

    // epilogue
#pragma unroll
    for (int i = 0; i < 4; i++) {
        int row0 = m0 + wm + i * 16 + g;
        int row1 = row0 + 8;
#pragma unroll
        for (int j = 0; j < 4; j++) {
            int col = n0 + wn + j * 8 + c * 2;
            if (row0 < NNODES)
                *(float2*)(Out + (size_t)row0 * 256 + col) =
                    make_float2(acc[i][j][0], acc[i][j][1]);
            if (row1 < NNODES)
                *(float2*)(Out + (size_t)row1 * 256 + col) =
                    make_float2(acc[i][j][2], acc[i][j][3]);
        }
    }
}

// ---------------- GATv2 attention: warp-per-dst, single-pass flash softmax ---
__global__ void k_attn(const float* __restrict__ XLR,
                       const float* __restrict__ att,
                       const float* __restrict__ bias,
                       float* __restrict__ H) {
    int warp = (blockIdx.x * blockDim.x + threadIdx.x) >> 5;
    int lane = threadIdx.x & 31;
    if (warp >= NNODES) return;
    int dst = warp;
    int c4 = lane << 2;

    float4 xr = *(const float4*)(XLR + (size_t)dst * 256 + 128 + c4);
    float4 av = *(const float4*)(att + c4);

    int beg = g_off[dst], end = g_off[dst + 1];

    float m = -1e30f, s = 0.f;
    float cx = 0.f, cy = 0.f, cz = 0.f, cw = 0.f;

    int src0 = g_csr[beg];
    float4 v = *(const float4*)(XLR + (size_t)src0 * 256 + c4);

    for (int jj = beg; jj < end; jj++) {
        float4 vn = v;
        if (jj + 1 < end) {
            int sn = g_csr[jj + 1];
            vn = *(const float4*)(XLR + (size_t)sn * 256 + c4);
        }
        float t0 = v.x + xr.x, t1 = v.y + xr.y, t2 = v.z + xr.z, t3 = v.w + xr.w;
        t0 = (t0 > 0.f) ? t0 : 0.2f * t0;
        t1 = (t1 > 0.f) ? t1 : 0.2f * t1;
        t2 = (t2 > 0.f) ? t2 : 0.2f * t2;
        t3 = (t3 > 0.f) ? t3 : 0.2f * t3;
        float p = av.x * t0 + av.y * t1 + av.z * t2 + av.w * t3;
        p += __shfl_xor_sync(0xffffffffu, p, 1);
        p += __shfl_xor_sync(0xffffffffu, p, 2);
        p += __shfl_xor_sync(0xffffffffu, p, 4);

        float nm = fmaxf(m, p);
        float sc = __expf(m - nm);
        float w  = __expf(p - nm);
        s  = s * sc + w;
        cx = cx * sc + w * v.x;
        cy = cy * sc + w * v.y;
        cz = cz * sc + w * v.z;
        cw = cw * sc + w * v.w;
        m = nm;
        v = vn;
    }
    float inv = 1.f / s;
    float4 bv = *(const float4*)(bias + c4);
    float4 o = make_float4(cx * inv + bv.x, cy * inv + bv.y,
                           cz * inv + bv.z, cw * inv + bv.w);
    *(float4*)(H + (size_t)dst * 128 + c4) = o;
}

// ---------------- down projection: Out[N,32] = H[N,128] @ W[32,128]^T + b ----
__global__ void k_down(const float* __restrict__ Hin,
                       const float* __restrict__ W,
                       const float* __restrict__ b,
                       float* __restrict__ Out) {
    __shared__ float Ws[128 * 33];   // Ws[k*33 + c], conflict-free
    __shared__ float Hs[8 * 128];
    int tid = threadIdx.x;
    for (int l = tid; l < 32 * 128; l += 256) {
        int c = l / 128, k = l % 128;
        Ws[k * 33 + c] = W[l];
    }
    int n0 = blockIdx.x * 8;
    for (int l = tid; l < 8 * 128; l += 256)
        Hs[l] = Hin[(size_t)n0 * 128 + l];
    __syncthreads();
    int nd = tid >> 5, c = tid & 31;
    float acc = 0.f;
#pragma unroll 16
    for (int k = 0; k < 128; k++)
        acc += Hs[nd * 128 + k] * Ws[k * 33 + c];
    Out[(size_t)(n0 + nd) * 32 + c] = acc + b[c];
}

// ---------------- launch -----------------------------------------------------
extern "C" void kernel_launch(void* const* d_in, const int* in_sizes, int n_in,
                              void* d_out, int out_size) {
    const float* x    = (const float*)d_in[0];
    const int*   ei   = (const int*)d_in[1];
    const float* Wl0  = (const float*)d_in[2];
    const float* Wr0  = (const float*)d_in[3];
    const float* att0 = (const float*)d_in[4];
    const float* b0   = (const float*)d_in[5];
    const float* Wl1  = (const float*)d_in[6];
    const float* Wr1  = (const float*)d_in[7];
    const float* att1 = (const float*)d_in[8];
    const float* b1   = (const float*)d_in[9];
    const float* dW   = (const float*)d_in[10];
    const float* db   = (const float*)d_in[11];
    float* out = (float*)d_out;

    float *xlr_p = nullptr, *h_p = nullptr;
    cudaGetSymbolAddress((void**)&xlr_p, g_XLR);
    cudaGetSymbolAddress((void**)&h_p, g_H);

    // CSR build (identical for both layers)
    k_deg_init<<<(NNODES + 255) / 256, 256>>>();
    k_deg_count<<<(NEDGES + 255) / 256, 256>>>(ei);
    k_scan<<<1, 1024>>>();
    k_fill<<<(ETOT + 255) / 256, 256>>>(ei);

    dim3 gg((NNODES + 127) / 128, 2);

    // layer 0
    k_gemm_tf32<<<gg, 256>>>(x, Wl0, Wr0, xlr_p, DIN);
    k_attn<<<(NNODES * 32 + 255) / 256, 256>>>(xlr_p, att0, b0, h_p);

    // layer 1
    k_gemm_tf32<<<gg, 256>>>(h_p, Wl1, Wr1, xlr_p, HID);
    k_attn<<<(NNODES * 32 + 255) / 256, 256>>>(xlr_p, att1, b1, h_p);

    // down proj
    k_down<<<NNODES / 8, 256>>>(h_p, dW, db, out);
}